// round 5
// baseline (speedup 1.0000x reference)
#include <cuda_runtime.h>
#include <cuda_bf16.h>
#include <math.h>
#include <stdint.h>

#define N_NODES 50000
#define N_EDGES 800000
#define HDIM    128
#define KDIM    256
#define NLAYERS 3
#define NGRAPHS 64
#define BN_EPS  1e-5f
#define SCAN_B  1024
#define NSCAN   ((N_NODES + SCAN_B - 1) / SCAN_B)
#define GEMM_GRID ((N_NODES + 127) / 128)

// ---------------- scratch (device globals) ----------------------------------
__device__ __align__(16) float g_agg [N_NODES * HDIM];
__device__ __align__(16) float g_buf0[N_NODES * HDIM];
__device__ __align__(16) float g_buf1[N_NODES * HDIM];
__device__ int   g_cnt     [N_NODES];
__device__ int   g_rowstart[N_NODES];
__device__ int   g_cursor  [N_NODES];
__device__ int   g_csr     [N_EDGES];
__device__ int   g_bsum    [NSCAN];
__device__ float g_invdeg  [N_NODES];
__device__ __align__(16) float g_affa[HDIM];
__device__ __align__(16) float g_affb[HDIM];
__device__ float g_bias_eff[HDIM];
__device__ float g_colsum[HDIM];
__device__ float g_colsq [HDIM];
__device__ float g_pool[NGRAPHS];
// per-layer B split: [n][k] bf16, k<128 = Wl, k>=128 = Wr*affa
__device__ __align__(16) __nv_bfloat16 g_bh[HDIM * KDIM];
__device__ __align__(16) __nv_bfloat16 g_bl[HDIM * KDIM];

// ---------------- helpers -----------------------------------------------------
__device__ __forceinline__ void hilo2(float2 v, uint32_t& h, uint32_t& l) {
    __nv_bfloat16 hx = __float2bfloat16_rn(v.x);
    __nv_bfloat16 hy = __float2bfloat16_rn(v.y);
    h = ((uint32_t)__bfloat16_as_ushort(hy) << 16) | (uint32_t)__bfloat16_as_ushort(hx);
    float rx = v.x - __bfloat162float(hx);
    float ry = v.y - __bfloat162float(hy);
    l = ((uint32_t)__bfloat16_as_ushort(__float2bfloat16_rn(ry)) << 16)
      | (uint32_t)__bfloat16_as_ushort(__float2bfloat16_rn(rx));
}
__device__ __forceinline__ void mma_bf16(float* d, const uint32_t* a,
                                         uint32_t b0, uint32_t b1) {
    asm volatile(
        "mma.sync.aligned.m16n8k16.row.col.f32.bf16.bf16.f32 "
        "{%0,%1,%2,%3}, {%4,%5,%6,%7}, {%8,%9}, {%0,%1,%2,%3};"
        : "+f"(d[0]), "+f"(d[1]), "+f"(d[2]), "+f"(d[3])
        : "r"(a[0]), "r"(a[1]), "r"(a[2]), "r"(a[3]), "r"(b0), "r"(b1));
}

// ---------------- CSR build ----------------------------------------------------
__global__ void count_kernel(const int* __restrict__ ei) {
    int e = blockIdx.x * blockDim.x + threadIdx.x;
    if (e < N_EDGES) atomicAdd(&g_cnt[ei[N_EDGES + e]], 1);
}
__global__ void scan1_kernel() {
    __shared__ int sh[SCAN_B];
    int i = blockIdx.x * SCAN_B + threadIdx.x;
    int v = (i < N_NODES) ? g_cnt[i] : 0;
    sh[threadIdx.x] = v;
    __syncthreads();
    for (int off = 1; off < SCAN_B; off <<= 1) {
        int t = (threadIdx.x >= off) ? sh[threadIdx.x - off] : 0;
        __syncthreads();
        sh[threadIdx.x] += t;
        __syncthreads();
    }
    if (i < N_NODES) g_rowstart[i] = sh[threadIdx.x] - v;
    if (threadIdx.x == SCAN_B - 1) g_bsum[blockIdx.x] = sh[SCAN_B - 1];
}
__global__ void scan2_kernel() {
    if (threadIdx.x == 0) {
        int run = 0;
        for (int b = 0; b < NSCAN; ++b) { int v = g_bsum[b]; g_bsum[b] = run; run += v; }
    }
}
__global__ void scan3_kernel() {
    int i = blockIdx.x * blockDim.x + threadIdx.x;
    if (i < N_NODES) {
        int rs = g_rowstart[i] + g_bsum[i / SCAN_B];
        g_rowstart[i] = rs;
        g_cursor[i]   = rs;
        g_invdeg[i]   = 1.0f / fmaxf((float)g_cnt[i], 1.0f);
    }
}
__global__ void fill_kernel(const int* __restrict__ ei) {
    int e = blockIdx.x * blockDim.x + threadIdx.x;
    if (e < N_EDGES) {
        int dst = ei[N_EDGES + e];
        int pos = atomicAdd(&g_cursor[dst], 1);
        g_csr[pos] = ei[e];
    }
}
__global__ void init_kernel() {
    int i = blockIdx.x * blockDim.x + threadIdx.x;
    if (i < HDIM) {
        g_affa[i] = 1.0f; g_affb[i] = 0.0f;
        g_colsum[i] = 0.0f; g_colsq[i] = 0.0f;
    }
    if (i < NGRAPHS) g_pool[i] = 0.0f;
}

// ---------------- gather-aggregate (no atomics) --------------------------------
__global__ void __launch_bounds__(256)
aggregate_kernel(const float* __restrict__ h) {
    __shared__ int sidx[8][32];
    int gt   = blockIdx.x * blockDim.x + threadIdx.x;
    int node = gt >> 5;
    int lane = gt & 31;
    int w    = threadIdx.x >> 5;
    if (node >= N_NODES) return;
    int base = g_rowstart[node];
    int deg  = g_cnt[node];
    const float4* h4 = (const float4*)h;
    float4 acc = make_float4(0.f, 0.f, 0.f, 0.f);
    for (int c = 0; c < deg; c += 32) {
        int s = (c + lane < deg) ? g_csr[base + c + lane] : 0;
        sidx[w][lane] = s;
        __syncwarp();
        int m = min(32, deg - c);
#pragma unroll 4
        for (int j = 0; j < m; ++j) {
            float4 v = h4[sidx[w][j] * 32 + lane];
            acc.x += v.x; acc.y += v.y; acc.z += v.z; acc.w += v.w;
        }
        __syncwarp();
    }
    float id = g_invdeg[node];
    float bs = (deg > 0) ? 1.0f : 0.0f;
    float4 a = ((const float4*)g_affa)[lane];
    float4 b = ((const float4*)g_affb)[lane];
    float4 r;
    r.x = fmaf(acc.x * id, a.x, b.x * bs);
    r.y = fmaf(acc.y * id, a.y, b.y * bs);
    r.z = fmaf(acc.z * id, a.z, b.z * bs);
    r.w = fmaf(acc.w * id, a.w, b.w * bs);
    ((float4*)g_agg)[node * 32 + lane] = r;
}

// ---------------- per-layer B prep: fold affine, split hi/lo -------------------
// g_bh/g_bl[n][k]: k<128 -> Wl[n,k]; k>=128 -> Wr[n,k-128]*affa[k-128]
__global__ void prep_kernel(const float* __restrict__ Wl,
                            const float* __restrict__ Wr,
                            const float* __restrict__ bias) {
    __shared__ float red[4];
    int j = blockIdx.x;   // output feature n
    int k = threadIdx.x;  // 0..127
    float a = g_affa[k], b = g_affb[k];
    float wl  = Wl[j * HDIM + k];
    float wre = Wr[j * HDIM + k] * a;

    __nv_bfloat16 h1 = __float2bfloat16_rn(wl);
    g_bh[j * KDIM + k] = h1;
    g_bl[j * KDIM + k] = __float2bfloat16_rn(wl - __bfloat162float(h1));
    __nv_bfloat16 h2 = __float2bfloat16_rn(wre);
    g_bh[j * KDIM + HDIM + k] = h2;
    g_bl[j * KDIM + HDIM + k] = __float2bfloat16_rn(wre - __bfloat162float(h2));

    float p = Wr[j * HDIM + k] * b;
#pragma unroll
    for (int off = 16; off; off >>= 1) p += __shfl_down_sync(0xffffffff, p, off);
    if ((k & 31) == 0) red[k >> 5] = p;
    __syncthreads();
    if (k == 0) g_bias_eff[j] = bias[j] + red[0] + red[1] + red[2] + red[3];
}

// ---------------- mma.sync dual GEMM (bf16 hi/lo x3, fp32-faithful) ------------
// y[i,:] = relu( [agg|hprev][i,:] @ [Wl|wr_eff]^T + bias_eff ) + fused BN stats
// CTA: 128 rows x 128 cols, 8 warps (4 row-groups x 2 col-groups), warp 32x64.
__global__ void __launch_bounds__(256)
gemm_mma_kernel(const float* __restrict__ hprev, float* __restrict__ yout) {
    __shared__ float s_cs[HDIM];
    __shared__ float s_sq[HDIM];

    const int tid   = threadIdx.x;
    const int lane  = tid & 31;
    const int warp  = tid >> 5;
    const int rwarp = blockIdx.x * 128 + (warp & 3) * 32;  // warp row base
    const int cwarp = (warp >> 2) * 64;                    // warp col base
    const int gr    = lane >> 2;                           // fragment row group 0..7
    const int c0    = (lane & 3) * 2;                      // fragment k/col pair base

    float acc[2][8][4];
#pragma unroll
    for (int mb = 0; mb < 2; ++mb)
#pragma unroll
        for (int nb = 0; nb < 8; ++nb)
#pragma unroll
            for (int q = 0; q < 4; ++q) acc[mb][nb][q] = 0.f;

    const __nv_bfloat16* Bh = g_bh;
    const __nv_bfloat16* Bl = g_bl;

#pragma unroll 1
    for (int s = 0; s < 16; ++s) {
        const float* A = (s < 8) ? g_agg : hprev;
        const int kloc = (s & 7) * 16;   // k within the 128-wide half for A
        const int kglb = s * 16;         // k within 256-wide B

        // ---- build A fragments (hi/lo) for mb=0,1 directly from global fp32 ----
        uint32_t ahi[2][4], alo[2][4];
#pragma unroll
        for (int mb = 0; mb < 2; ++mb) {
            int r0 = rwarp + mb * 16 + gr;
            int r1 = r0 + 8;
            float2 x00 = make_float2(0.f, 0.f), x01 = x00, x10 = x00, x11 = x00;
            if (r0 < N_NODES) {
                x00 = *(const float2*)(A + (size_t)r0 * HDIM + kloc + c0);
                x01 = *(const float2*)(A + (size_t)r0 * HDIM + kloc + c0 + 8);
            }
            if (r1 < N_NODES) {
                x10 = *(const float2*)(A + (size_t)r1 * HDIM + kloc + c0);
                x11 = *(const float2*)(A + (size_t)r1 * HDIM + kloc + c0 + 8);
            }
            hilo2(x00, ahi[mb][0], alo[mb][0]);
            hilo2(x10, ahi[mb][1], alo[mb][1]);
            hilo2(x01, ahi[mb][2], alo[mb][2]);
            hilo2(x11, ahi[mb][3], alo[mb][3]);
        }

        // ---- per 8-col block: load B frags, 3 passes (hh, lh, hl) ----
#pragma unroll
        for (int nb = 0; nb < 8; ++nb) {
            int n = cwarp + nb * 8 + gr;
            const __nv_bfloat16* ph = Bh + (size_t)n * KDIM + kglb + c0;
            const __nv_bfloat16* pl = Bl + (size_t)n * KDIM + kglb + c0;
            uint32_t bh0 = *(const uint32_t*)ph;
            uint32_t bh1 = *(const uint32_t*)(ph + 8);
            uint32_t bl0 = *(const uint32_t*)pl;
            uint32_t bl1 = *(const uint32_t*)(pl + 8);
#pragma unroll
            for (int mb = 0; mb < 2; ++mb) {
                mma_bf16(acc[mb][nb], ahi[mb], bh0, bh1);
                mma_bf16(acc[mb][nb], alo[mb], bh0, bh1);
                mma_bf16(acc[mb][nb], ahi[mb], bl0, bl1);
            }
        }
    }

    // ---- epilogue: bias + relu + store + BN stats ----
    float cs[16], sq[16];
#pragma unroll
    for (int i = 0; i < 16; ++i) { cs[i] = 0.f; sq[i] = 0.f; }

#pragma unroll
    for (int nb = 0; nb < 8; ++nb) {
        int n0 = cwarp + nb * 8 + c0;
        float bx = g_bias_eff[n0], by = g_bias_eff[n0 + 1];
#pragma unroll
        for (int mb = 0; mb < 2; ++mb) {
            int r0 = rwarp + mb * 16 + gr;
#pragma unroll
            for (int half = 0; half < 2; ++half) {
                int r = r0 + half * 8;
                if (r < N_NODES) {
                    float vx = fmaxf(acc[mb][nb][half * 2 + 0] + bx, 0.f);
                    float vy = fmaxf(acc[mb][nb][half * 2 + 1] + by, 0.f);
                    *(float2*)(yout + (size_t)r * HDIM + n0) = make_float2(vx, vy);
                    cs[nb * 2 + 0] += vx; sq[nb * 2 + 0] += vx * vx;
                    cs[nb * 2 + 1] += vy; sq[nb * 2 + 1] += vy * vy;
                }
            }
        }
    }

    if (tid < HDIM) { s_cs[tid] = 0.f; s_sq[tid] = 0.f; }
    __syncthreads();
#pragma unroll
    for (int nb = 0; nb < 8; ++nb) {
        int n0 = cwarp + nb * 8 + c0;
        atomicAdd(&s_cs[n0 + 0], cs[nb * 2 + 0]);
        atomicAdd(&s_sq[n0 + 0], sq[nb * 2 + 0]);
        atomicAdd(&s_cs[n0 + 1], cs[nb * 2 + 1]);
        atomicAdd(&s_sq[n0 + 1], sq[nb * 2 + 1]);
    }
    __syncthreads();
    if (tid < HDIM) {
        atomicAdd(&g_colsum[tid], s_cs[tid]);
        atomicAdd(&g_colsq [tid], s_sq[tid]);
    }
}

// ---------------- BN finalize -> affine ------------------------------------------
__global__ void finalize_kernel(const float* __restrict__ gamma,
                                const float* __restrict__ beta) {
    int j = threadIdx.x;
    if (j >= HDIM) return;
    float s = g_colsum[j], q = g_colsq[j];
    float mu  = s / (float)N_NODES;
    float var = q / (float)N_NODES - mu * mu;
    float a = gamma[j] * rsqrtf(var + BN_EPS);
    float b = beta[j] - mu * a;
    g_affa[j] = a;
    g_affb[j] = b;
    g_colsum[j] = 0.f;
    g_colsq [j] = 0.f;
}

// ---------------- pooling fused with FC -------------------------------------------
__global__ void pool_kernel(const float* __restrict__ h,
                            const int* __restrict__ batch,
                            const float* __restrict__ fcw) {
    int gt   = blockIdx.x * blockDim.x + threadIdx.x;
    int node = gt >> 5;
    int lane = gt & 31;
    if (node >= N_NODES) return;
    float4 v = ((const float4*)h)[node * 32 + lane];
    float4 a = ((const float4*)g_affa)[lane];
    float4 b = ((const float4*)g_affb)[lane];
    float4 w = ((const float4*)fcw)[lane];
    float d = fmaf(v.x, a.x, b.x) * w.x
            + fmaf(v.y, a.y, b.y) * w.y
            + fmaf(v.z, a.z, b.z) * w.z
            + fmaf(v.w, a.w, b.w) * w.w;
#pragma unroll
    for (int off = 16; off; off >>= 1)
        d += __shfl_down_sync(0xffffffff, d, off);
    if (lane == 0) atomicAdd(&g_pool[batch[node]], d);
}

__global__ void out_kernel(const float* __restrict__ fcb, float* __restrict__ out) {
    int g = threadIdx.x;
    if (g < NGRAPHS) out[g] = 1.0f / (1.0f + expf(-(g_pool[g] + fcb[0])));
}

// ---------------- host launcher (graph-capturable) --------------------------------
extern "C" void kernel_launch(void* const* d_in, const int* in_sizes, int n_in,
                              void* d_out, int out_size) {
    const float* x        = (const float*)d_in[0];
    const int*   ei       = (const int*)d_in[1];
    /* d_in[2] edge_attr unused */
    const int*   batch    = (const int*)d_in[3];
    const float* lin_l_w  = (const float*)d_in[4];
    const float* lin_l_b  = (const float*)d_in[5];
    const float* lin_r_w  = (const float*)d_in[6];
    const float* bn_gamma = (const float*)d_in[7];
    const float* bn_beta  = (const float*)d_in[8];
    const float* fc_w     = (const float*)d_in[9];
    const float* fc_b     = (const float*)d_in[10];
    float*       out      = (float*)d_out;

    void *p_cnt, *p_b0, *p_b1;
    cudaGetSymbolAddress(&p_cnt, g_cnt);
    cudaGetSymbolAddress(&p_b0,  g_buf0);
    cudaGetSymbolAddress(&p_b1,  g_buf1);
    float* bufs[2] = { (float*)p_b0, (float*)p_b1 };

    // CSR build (once per launch)
    cudaMemsetAsync(p_cnt, 0, N_NODES * sizeof(int));
    count_kernel<<<(N_EDGES + 255) / 256, 256>>>(ei);
    scan1_kernel<<<NSCAN, SCAN_B>>>();
    scan2_kernel<<<1, 32>>>();
    scan3_kernel<<<(N_NODES + 255) / 256, 256>>>();
    fill_kernel<<<(N_EDGES + 255) / 256, 256>>>(ei);
    init_kernel<<<1, 256>>>();

    const float* hprev = x;
    for (int l = 0; l < NLAYERS; ++l) {
        float* yout = bufs[l & 1];
        aggregate_kernel<<<(N_NODES * 32 + 255) / 256, 256>>>(hprev);
        prep_kernel<<<HDIM, HDIM>>>(lin_l_w + (size_t)l * HDIM * HDIM,
                                    lin_r_w + (size_t)l * HDIM * HDIM,
                                    lin_l_b + (size_t)l * HDIM);
        gemm_mma_kernel<<<GEMM_GRID, 256>>>(hprev, yout);
        finalize_kernel<<<1, HDIM>>>(bn_gamma + (size_t)l * HDIM,
                                     bn_beta  + (size_t)l * HDIM);
        hprev = yout;
    }
    pool_kernel<<<(N_NODES * 32 + 255) / 256, 256>>>(hprev, batch, fc_w);
    out_kernel<<<1, NGRAPHS>>>(fc_b, out);
}

// round 7
// speedup vs baseline: 1.5270x; 1.5270x over previous
#include <cuda_runtime.h>
#include <cuda_bf16.h>
#include <math.h>

#define N_NODES 50000
#define N_EDGES 800000
#define HDIM    128
#define NLAYERS 3
#define NGRAPHS 64
#define BN_EPS  1e-5f
#define SCAN_B  1024
#define NSCAN   ((N_NODES + SCAN_B - 1) / SCAN_B)

typedef unsigned long long ull;

// ---------------- scratch (device globals) ----------------------------------
__device__ __align__(16) float g_agg [N_NODES * HDIM];
__device__ __align__(16) float g_buf0[N_NODES * HDIM];
__device__ __align__(16) float g_buf1[N_NODES * HDIM];
__device__ int   g_cnt     [N_NODES];
__device__ int   g_rowstart[N_NODES];
__device__ int   g_cursor  [N_NODES];
__device__ int   g_csr     [N_EDGES];
__device__ int   g_bsum    [NSCAN];
__device__ float g_invdeg  [N_NODES];
__device__ __align__(16) float g_affa[HDIM];
__device__ __align__(16) float g_affb[HDIM];
__device__ __align__(16) float g_wr_eff [HDIM * HDIM];
__device__ float g_bias_eff[HDIM];
__device__ float g_colsum[HDIM];
__device__ float g_colsq [HDIM];
__device__ float g_pool[NGRAPHS];

// ---------------- f32x2 helpers ---------------------------------------------
__device__ __forceinline__ ull fma2(ull a, ull b, ull c) {
    ull d;
    asm("fma.rn.f32x2 %0, %1, %2, %3;" : "=l"(d) : "l"(a), "l"(b), "l"(c));
    return d;
}
__device__ __forceinline__ ull dup2(float x) {
    ull d;
    asm("mov.b64 %0, {%1, %1};" : "=l"(d) : "f"(x));
    return d;
}

// ---------------- init: zero cnt + identity affine + zero stats/pool ---------
__global__ void initzero_kernel() {
    int i = blockIdx.x * blockDim.x + threadIdx.x;
    if (i < N_NODES) g_cnt[i] = 0;
    if (i < HDIM) {
        g_affa[i] = 1.0f; g_affb[i] = 0.0f;
        g_colsum[i] = 0.0f; g_colsq[i] = 0.0f;
    }
    if (i < NGRAPHS) g_pool[i] = 0.0f;
}

// ---------------- CSR build --------------------------------------------------
__global__ void count_kernel(const int* __restrict__ ei) {
    int e = blockIdx.x * blockDim.x + threadIdx.x;
    if (e < N_EDGES) atomicAdd(&g_cnt[ei[N_EDGES + e]], 1);
}

__global__ void scan1_kernel() {
    __shared__ int sh[SCAN_B];
    int i = blockIdx.x * SCAN_B + threadIdx.x;
    int v = (i < N_NODES) ? g_cnt[i] : 0;
    sh[threadIdx.x] = v;
    __syncthreads();
    for (int off = 1; off < SCAN_B; off <<= 1) {
        int t = (threadIdx.x >= off) ? sh[threadIdx.x - off] : 0;
        __syncthreads();
        sh[threadIdx.x] += t;
        __syncthreads();
    }
    if (i < N_NODES) g_rowstart[i] = sh[threadIdx.x] - v;  // exclusive within block
    if (threadIdx.x == SCAN_B - 1) g_bsum[blockIdx.x] = sh[SCAN_B - 1];
}

// scan2 folded in: every block sums the (tiny) bsum prefix itself.
__global__ void scan23_kernel() {
    __shared__ int s_pre[NSCAN];
    int t = threadIdx.x;
    if (t < NSCAN) s_pre[t] = g_bsum[t];
    __syncthreads();
    if (t == 0) {
        int run = 0;
#pragma unroll
        for (int b = 0; b < NSCAN; ++b) { int v = s_pre[b]; s_pre[b] = run; run += v; }
    }
    __syncthreads();
    int i = blockIdx.x * blockDim.x + t;
    if (i < N_NODES) {
        int rs = g_rowstart[i] + s_pre[i / SCAN_B];
        g_rowstart[i] = rs;
        g_cursor[i]   = rs;
        g_invdeg[i]   = 1.0f / fmaxf((float)g_cnt[i], 1.0f);
    }
}

__global__ void fill_kernel(const int* __restrict__ ei) {
    int e = blockIdx.x * blockDim.x + threadIdx.x;
    if (e < N_EDGES) {
        int dst = ei[N_EDGES + e];
        int pos = atomicAdd(&g_cursor[dst], 1);
        g_csr[pos] = ei[e];
    }
}

// ---------------- gather-aggregate (no atomics) -----------------------------
// one warp per dst node; lane owns a float4 slice of the 128-dim feature.
__global__ void __launch_bounds__(256)
aggregate_kernel(const float* __restrict__ h) {
    __shared__ int sidx[8][32];
    int gt   = blockIdx.x * blockDim.x + threadIdx.x;
    int node = gt >> 5;
    int lane = gt & 31;
    int w    = threadIdx.x >> 5;
    if (node >= N_NODES) return;

    int base = g_rowstart[node];
    int deg  = g_cnt[node];
    const float4* h4 = (const float4*)h;

    float4 acc = make_float4(0.f, 0.f, 0.f, 0.f);
    for (int c = 0; c < deg; c += 32) {
        int s = (c + lane < deg) ? g_csr[base + c + lane] : 0;
        sidx[w][lane] = s;
        __syncwarp();
        int m = min(32, deg - c);
#pragma unroll 4
        for (int j = 0; j < m; ++j) {
            float4 v = h4[sidx[w][j] * 32 + lane];
            acc.x += v.x; acc.y += v.y; acc.z += v.z; acc.w += v.w;
        }
        __syncwarp();
    }
    float id = g_invdeg[node];
    float bs = (deg > 0) ? 1.0f : 0.0f;
    float4 a = ((const float4*)g_affa)[lane];
    float4 b = ((const float4*)g_affb)[lane];
    float4 r;
    r.x = fmaf(acc.x * id, a.x, b.x * bs);
    r.y = fmaf(acc.y * id, a.y, b.y * bs);
    r.z = fmaf(acc.z * id, a.z, b.z * bs);
    r.w = fmaf(acc.w * id, a.w, b.w * bs);
    ((float4*)g_agg)[node * 32 + lane] = r;
}

// ---------------- fold BN affine into Wr + bias ------------------------------
__global__ void prep_kernel(const float* __restrict__ Wr,
                            const float* __restrict__ bias) {
    __shared__ float red[4];
    int j = blockIdx.x;
    int k = threadIdx.x;
    float w = Wr[j * HDIM + k];
    float a = g_affa[k], b = g_affb[k];
    g_wr_eff[j * HDIM + k] = w * a;
    float p = w * b;
#pragma unroll
    for (int off = 16; off; off >>= 1) p += __shfl_down_sync(0xffffffff, p, off);
    if ((k & 31) == 0) red[k >> 5] = p;
    __syncthreads();
    if (k == 0) g_bias_eff[j] = bias[j] + red[0] + red[1] + red[2] + red[3];
}

// ---------------- fused dual GEMM (f32x2) + bias + relu + BN stats -----------
#define AS_STRIDE 66
__global__ void __launch_bounds__(256)
gemm_kernel(const float* __restrict__ hprev,
            const float* __restrict__ Wl,
            float* __restrict__ yout) {
    __shared__ __align__(16) float As[32 * AS_STRIDE];  // [k][row]
    __shared__ __align__(16) float Bs[32 * 132];        // [k][col]
    __shared__ float s_cs[HDIM];
    __shared__ float s_sq[HDIM];

    const int tid  = threadIdx.x;
    const int ty   = tid >> 5;
    const int tx   = tid & 31;
    const int row0 = blockIdx.x * 64;

    ull acc2[4][4];
#pragma unroll
    for (int p = 0; p < 4; ++p)
#pragma unroll
        for (int j = 0; j < 4; ++j) acc2[p][j] = 0ull;

#pragma unroll 1
    for (int t = 0; t < 8; ++t) {
        const int  kk     = t * 32;
        const bool second = (kk >= 128);
        const int  kloc   = second ? kk - 128 : kk;
        const float* A = second ? hprev : g_agg;
        const float* W = second ? g_wr_eff : Wl;

#pragma unroll
        for (int i = 0; i < 2; ++i) {
            int f  = tid + 256 * i;
            int r  = f >> 3;
            int c4 = f & 7;
            int grow = row0 + r;
            float4 v = make_float4(0.f, 0.f, 0.f, 0.f);
            if (grow < N_NODES)
                v = *((const float4*)(A + (size_t)grow * HDIM + kloc + c4 * 4));
            As[(c4 * 4 + 0) * AS_STRIDE + r] = v.x;
            As[(c4 * 4 + 1) * AS_STRIDE + r] = v.y;
            As[(c4 * 4 + 2) * AS_STRIDE + r] = v.z;
            As[(c4 * 4 + 3) * AS_STRIDE + r] = v.w;
        }
#pragma unroll
        for (int i = 0; i < 4; ++i) {
            int f  = tid + 256 * i;
            int j  = f >> 3;
            int kq = f & 7;
            float4 w = *((const float4*)(W + (size_t)j * HDIM + kloc + kq * 4));
            Bs[(kq * 4 + 0) * 132 + j] = w.x;
            Bs[(kq * 4 + 1) * 132 + j] = w.y;
            Bs[(kq * 4 + 2) * 132 + j] = w.z;
            Bs[(kq * 4 + 3) * 132 + j] = w.w;
        }
        __syncthreads();

#pragma unroll
        for (int k = 0; k < 32; ++k) {
            const ull* ap = (const ull*)(As + k * AS_STRIDE + ty * 8);
            ull a0 = ap[0], a1 = ap[1], a2 = ap[2], a3 = ap[3];
            float4 bv = *((const float4*)(Bs + k * 132 + tx * 4));
            ull b0 = dup2(bv.x), b1 = dup2(bv.y), b2 = dup2(bv.z), b3 = dup2(bv.w);
            acc2[0][0] = fma2(a0, b0, acc2[0][0]);
            acc2[0][1] = fma2(a0, b1, acc2[0][1]);
            acc2[0][2] = fma2(a0, b2, acc2[0][2]);
            acc2[0][3] = fma2(a0, b3, acc2[0][3]);
            acc2[1][0] = fma2(a1, b0, acc2[1][0]);
            acc2[1][1] = fma2(a1, b1, acc2[1][1]);
            acc2[1][2] = fma2(a1, b2, acc2[1][2]);
            acc2[1][3] = fma2(a1, b3, acc2[1][3]);
            acc2[2][0] = fma2(a2, b0, acc2[2][0]);
            acc2[2][1] = fma2(a2, b1, acc2[2][1]);
            acc2[2][2] = fma2(a2, b2, acc2[2][2]);
            acc2[2][3] = fma2(a2, b3, acc2[2][3]);
            acc2[3][0] = fma2(a3, b0, acc2[3][0]);
            acc2[3][1] = fma2(a3, b1, acc2[3][1]);
            acc2[3][2] = fma2(a3, b2, acc2[3][2]);
            acc2[3][3] = fma2(a3, b3, acc2[3][3]);
        }
        __syncthreads();
    }

    const int col = tx * 4;
    float4 bi = *((const float4*)(g_bias_eff + col));
    float cs[4] = {0.f, 0.f, 0.f, 0.f};
    float sq[4] = {0.f, 0.f, 0.f, 0.f};
#pragma unroll
    for (int p = 0; p < 4; ++p) {
        float lo[4], hi[4];
#pragma unroll
        for (int j = 0; j < 4; ++j) {
            lo[j] = __uint_as_float((unsigned)(acc2[p][j] & 0xffffffffull));
            hi[j] = __uint_as_float((unsigned)(acc2[p][j] >> 32));
        }
        int grow = row0 + ty * 8 + 2 * p;
        if (grow < N_NODES) {
            float4 r;
            r.x = fmaxf(lo[0] + bi.x, 0.f);
            r.y = fmaxf(lo[1] + bi.y, 0.f);
            r.z = fmaxf(lo[2] + bi.z, 0.f);
            r.w = fmaxf(lo[3] + bi.w, 0.f);
            *((float4*)(yout + (size_t)grow * HDIM + col)) = r;
            cs[0] += r.x; sq[0] += r.x * r.x;
            cs[1] += r.y; sq[1] += r.y * r.y;
            cs[2] += r.z; sq[2] += r.z * r.z;
            cs[3] += r.w; sq[3] += r.w * r.w;
        }
        if (grow + 1 < N_NODES) {
            float4 r;
            r.x = fmaxf(hi[0] + bi.x, 0.f);
            r.y = fmaxf(hi[1] + bi.y, 0.f);
            r.z = fmaxf(hi[2] + bi.z, 0.f);
            r.w = fmaxf(hi[3] + bi.w, 0.f);
            *((float4*)(yout + (size_t)(grow + 1) * HDIM + col)) = r;
            cs[0] += r.x; sq[0] += r.x * r.x;
            cs[1] += r.y; sq[1] += r.y * r.y;
            cs[2] += r.z; sq[2] += r.z * r.z;
            cs[3] += r.w; sq[3] += r.w * r.w;
        }
    }
    if (tid < HDIM) { s_cs[tid] = 0.f; s_sq[tid] = 0.f; }
    __syncthreads();
#pragma unroll
    for (int j = 0; j < 4; ++j) {
        atomicAdd(&s_cs[col + j], cs[j]);
        atomicAdd(&s_sq[col + j], sq[j]);
    }
    __syncthreads();
    if (tid < HDIM) {
        atomicAdd(&g_colsum[tid], s_cs[tid]);
        atomicAdd(&g_colsq [tid], s_sq[tid]);
    }
}

// ---------------- BN finalize -> affine --------------------------------------
__global__ void finalize_kernel(const float* __restrict__ gamma,
                                const float* __restrict__ beta) {
    int j = threadIdx.x;
    if (j >= HDIM) return;
    float s  = g_colsum[j];
    float q  = g_colsq[j];
    float mu  = s / (float)N_NODES;
    float var = q / (float)N_NODES - mu * mu;
    float a = gamma[j] * rsqrtf(var + BN_EPS);
    float b = beta[j] - mu * a;
    g_affa[j] = a;
    g_affb[j] = b;
    g_colsum[j] = 0.f;
    g_colsq [j] = 0.f;
}

// ---------------- pooling fused with FC --------------------------------------
__global__ void pool_kernel(const float* __restrict__ h,
                            const int* __restrict__ batch,
                            const float* __restrict__ fcw) {
    int gt   = blockIdx.x * blockDim.x + threadIdx.x;
    int node = gt >> 5;
    int lane = gt & 31;
    if (node >= N_NODES) return;
    float4 v = ((const float4*)h)[node * 32 + lane];
    float4 a = ((const float4*)g_affa)[lane];
    float4 b = ((const float4*)g_affb)[lane];
    float4 w = ((const float4*)fcw)[lane];
    float d = fmaf(v.x, a.x, b.x) * w.x
            + fmaf(v.y, a.y, b.y) * w.y
            + fmaf(v.z, a.z, b.z) * w.z
            + fmaf(v.w, a.w, b.w) * w.w;
#pragma unroll
    for (int off = 16; off; off >>= 1)
        d += __shfl_down_sync(0xffffffff, d, off);
    if (lane == 0) atomicAdd(&g_pool[batch[node]], d);
}

__global__ void out_kernel(const float* __restrict__ fcb, float* __restrict__ out) {
    int g = threadIdx.x;
    if (g < NGRAPHS) out[g] = 1.0f / (1.0f + expf(-(g_pool[g] + fcb[0])));
}

// ---------------- host launcher (graph-capturable) --------------------------
extern "C" void kernel_launch(void* const* d_in, const int* in_sizes, int n_in,
                              void* d_out, int out_size) {
    const float* x        = (const float*)d_in[0];
    const int*   ei       = (const int*)d_in[1];
    /* d_in[2] edge_attr unused */
    const int*   batch    = (const int*)d_in[3];
    const float* lin_l_w  = (const float*)d_in[4];
    const float* lin_l_b  = (const float*)d_in[5];
    const float* lin_r_w  = (const float*)d_in[6];
    const float* bn_gamma = (const float*)d_in[7];
    const float* bn_beta  = (const float*)d_in[8];
    const float* fc_w     = (const float*)d_in[9];
    const float* fc_b     = (const float*)d_in[10];
    float*       out      = (float*)d_out;

    void *p_b0, *p_b1;
    cudaGetSymbolAddress(&p_b0, g_buf0);
    cudaGetSymbolAddress(&p_b1, g_buf1);
    float* bufs[2] = { (float*)p_b0, (float*)p_b1 };

    // CSR build; launch index 5 = first aggregate (ncu samples it)
    initzero_kernel<<<(N_NODES + 255) / 256, 256>>>();          // 0
    count_kernel<<<(N_EDGES + 255) / 256, 256>>>(ei);           // 1
    scan1_kernel<<<NSCAN, SCAN_B>>>();                          // 2
    scan23_kernel<<<(N_NODES + 255) / 256, 256>>>();            // 3
    fill_kernel<<<(N_EDGES + 255) / 256, 256>>>(ei);            // 4

    const float* hprev = x;
    for (int l = 0; l < NLAYERS; ++l) {
        float* yout = bufs[l & 1];
        aggregate_kernel<<<(N_NODES * 32 + 255) / 256, 256>>>(hprev);   // 5 (l=0)
        prep_kernel<<<HDIM, HDIM>>>(lin_r_w + (size_t)l * HDIM * HDIM,
                                    lin_l_b + (size_t)l * HDIM);
        gemm_kernel<<<(N_NODES + 63) / 64, 256>>>(
            hprev,
            lin_l_w + (size_t)l * HDIM * HDIM,
            yout);
        finalize_kernel<<<1, HDIM>>>(bn_gamma + (size_t)l * HDIM,
                                     bn_beta  + (size_t)l * HDIM);
        hprev = yout;
    }
    pool_kernel<<<(N_NODES * 32 + 255) / 256, 256>>>(hprev, batch, fc_w);
    out_kernel<<<1, NGRAPHS>>>(fc_b, out);
}

// round 9
// speedup vs baseline: 1.5341x; 1.0046x over previous
#include <cuda_runtime.h>
#include <cuda_bf16.h>
#include <math.h>

#define N_NODES 50000
#define N_EDGES 800000
#define HDIM    128
#define NLAYERS 3
#define NGRAPHS 64
#define BN_EPS  1e-5f
#define SCAN_B  1024
#define NSCAN   ((N_NODES + SCAN_B - 1) / SCAN_B)

typedef unsigned long long ull;

// ---------------- scratch (device globals) ----------------------------------
__device__ __align__(16) float g_buf0[N_NODES * HDIM];
__device__ __align__(16) float g_buf1[N_NODES * HDIM];
__device__ int   g_cnt     [N_NODES];
__device__ int   g_rowstart[N_NODES];
__device__ int   g_cursor  [N_NODES];
__device__ int   g_csr     [N_EDGES];
__device__ int   g_bsum    [NSCAN];
__device__ float g_invdeg  [N_NODES];
__device__ __align__(16) float g_affa[HDIM];
__device__ __align__(16) float g_affb[HDIM];
__device__ __align__(16) float g_wr_eff [HDIM * HDIM];
__device__ float g_bias_eff[HDIM];
__device__ float g_colsum[HDIM];
__device__ float g_colsq [HDIM];
__device__ float g_pool[NGRAPHS];

// ---------------- f32x2 helpers ---------------------------------------------
__device__ __forceinline__ ull fma2(ull a, ull b, ull c) {
    ull d;
    asm("fma.rn.f32x2 %0, %1, %2, %3;" : "=l"(d) : "l"(a), "l"(b), "l"(c));
    return d;
}
__device__ __forceinline__ ull dup2(float x) {
    ull d;
    asm("mov.b64 %0, {%1, %1};" : "=l"(d) : "f"(x));
    return d;
}

// ---------------- init -------------------------------------------------------
__global__ void initzero_kernel() {
    int i = blockIdx.x * blockDim.x + threadIdx.x;
    if (i < N_NODES) g_cnt[i] = 0;
    if (i < HDIM) {
        g_affa[i] = 1.0f; g_affb[i] = 0.0f;
        g_colsum[i] = 0.0f; g_colsq[i] = 0.0f;
    }
    if (i < NGRAPHS) g_pool[i] = 0.0f;
}

// ---------------- CSR build --------------------------------------------------
__global__ void count_kernel(const int* __restrict__ ei) {
    int e = blockIdx.x * blockDim.x + threadIdx.x;
    if (e < N_EDGES) atomicAdd(&g_cnt[ei[N_EDGES + e]], 1);
}

__global__ void scan1_kernel() {
    __shared__ int sh[SCAN_B];
    int i = blockIdx.x * SCAN_B + threadIdx.x;
    int v = (i < N_NODES) ? g_cnt[i] : 0;
    sh[threadIdx.x] = v;
    __syncthreads();
    for (int off = 1; off < SCAN_B; off <<= 1) {
        int t = (threadIdx.x >= off) ? sh[threadIdx.x - off] : 0;
        __syncthreads();
        sh[threadIdx.x] += t;
        __syncthreads();
    }
    if (i < N_NODES) g_rowstart[i] = sh[threadIdx.x] - v;
    if (threadIdx.x == SCAN_B - 1) g_bsum[blockIdx.x] = sh[SCAN_B - 1];
}

__global__ void scan23_kernel() {
    __shared__ int s_pre[NSCAN];
    int t = threadIdx.x;
    if (t < NSCAN) s_pre[t] = g_bsum[t];
    __syncthreads();
    if (t == 0) {
        int run = 0;
#pragma unroll
        for (int b = 0; b < NSCAN; ++b) { int v = s_pre[b]; s_pre[b] = run; run += v; }
    }
    __syncthreads();
    int i = blockIdx.x * blockDim.x + t;
    if (i < N_NODES) {
        int rs = g_rowstart[i] + s_pre[i / SCAN_B];
        g_rowstart[i] = rs;
        g_cursor[i]   = rs;
        g_invdeg[i]   = 1.0f / fmaxf((float)g_cnt[i], 1.0f);
    }
}

__global__ void fill_kernel(const int* __restrict__ ei) {
    int e = blockIdx.x * blockDim.x + threadIdx.x;
    if (e < N_EDGES) {
        int dst = ei[N_EDGES + e];
        int pos = atomicAdd(&g_cursor[dst], 1);
        g_csr[pos] = ei[e];
    }
}

// ---------------- fold BN affine into Wr + bias ------------------------------
__global__ void prep_kernel(const float* __restrict__ Wr,
                            const float* __restrict__ bias) {
    __shared__ float red[4];
    int j = blockIdx.x;
    int k = threadIdx.x;
    float w = Wr[j * HDIM + k];
    float a = g_affa[k], b = g_affb[k];
    g_wr_eff[j * HDIM + k] = w * a;
    float p = w * b;
#pragma unroll
    for (int off = 16; off; off >>= 1) p += __shfl_down_sync(0xffffffff, p, off);
    if ((k & 31) == 0) red[k >> 5] = p;
    __syncthreads();
    if (k == 0) g_bias_eff[j] = bias[j] + red[0] + red[1] + red[2] + red[3];
}

// ---------------- FUSED gather-aggregate + dual GEMM + relu + BN stats -------
// Per CTA: 64 rows. Phase 1: warp w gathers rows w*8..w*8+7 (mean over CSR
// neighbors, BN affine applied) -> transposed smem tile sAggT[k][row].
// Phase 2: 64x128 dual-K GEMM; K-half 0 reads sAggT, K-half 1 reads hprev.
#define AS_STRIDE 66
// dynamic smem layout (floats)
#define OFF_SAGG 0                         // 128 * 66
#define OFF_AS   (128 * AS_STRIDE)         // 32 * 66
#define OFF_BS   (OFF_AS + 32 * AS_STRIDE) // 32 * 132
#define OFF_CS   (OFF_BS + 32 * 132)       // 128
#define OFF_SQ   (OFF_CS + 128)            // 128
#define OFF_SIDX (OFF_SQ + 128)            // 8*32 ints
#define SMEM_FLOATS (OFF_SIDX + 8 * 32)
#define SMEM_BYTES  (SMEM_FLOATS * 4)

__global__ void __launch_bounds__(256)
gemm_fused_kernel(const float* __restrict__ hprev,
                  const float* __restrict__ Wl,
                  float* __restrict__ yout) {
    extern __shared__ __align__(16) float smem[];
    float* sAggT = smem + OFF_SAGG;
    float* As    = smem + OFF_AS;
    float* Bs    = smem + OFF_BS;
    float* s_cs  = smem + OFF_CS;
    float* s_sq  = smem + OFF_SQ;
    int*   sidx  = (int*)(smem + OFF_SIDX);

    const int tid  = threadIdx.x;
    const int ty   = tid >> 5;       // warp 0..7
    const int tx   = tid & 31;       // lane
    const int row0 = blockIdx.x * 64;

    // ================= phase 1: gather-aggregate into sAggT ==================
    {
        const float4* h4 = (const float4*)hprev;
        int* my_sidx = sidx + ty * 32;
        const float4 a4 = ((const float4*)g_affa)[tx];
        const float4 b4 = ((const float4*)g_affb)[tx];
#pragma unroll 1
        for (int i = 0; i < 8; ++i) {
            int lrow = ty * 8 + i;
            int grow = row0 + lrow;
            int base = 0, deg = 0;
            float id = 0.f;
            if (grow < N_NODES) {
                base = g_rowstart[grow];
                deg  = g_cnt[grow];
                id   = g_invdeg[grow];
            }
            float4 acc = make_float4(0.f, 0.f, 0.f, 0.f);
            for (int c = 0; c < deg; c += 32) {
                int s = (c + tx < deg) ? g_csr[base + c + tx] : 0;
                my_sidx[tx] = s;
                __syncwarp();
                int m = min(32, deg - c);
#pragma unroll 4
                for (int j = 0; j < m; ++j) {
                    float4 v = h4[my_sidx[j] * 32 + tx];
                    acc.x += v.x; acc.y += v.y; acc.z += v.z; acc.w += v.w;
                }
                __syncwarp();
            }
            float bs = (deg > 0) ? 1.0f : 0.0f;
            float4 r;
            r.x = fmaf(acc.x * id, a4.x, b4.x * bs);
            r.y = fmaf(acc.y * id, a4.y, b4.y * bs);
            r.z = fmaf(acc.z * id, a4.z, b4.z * bs);
            r.w = fmaf(acc.w * id, a4.w, b4.w * bs);
            // transposed store: sAggT[k][lrow], k = tx*4 + j
            sAggT[(tx * 4 + 0) * AS_STRIDE + lrow] = r.x;
            sAggT[(tx * 4 + 1) * AS_STRIDE + lrow] = r.y;
            sAggT[(tx * 4 + 2) * AS_STRIDE + lrow] = r.z;
            sAggT[(tx * 4 + 3) * AS_STRIDE + lrow] = r.w;
        }
    }
    __syncthreads();

    // ================= phase 2: dual GEMM ====================================
    ull acc2[4][4];
#pragma unroll
    for (int p = 0; p < 4; ++p)
#pragma unroll
        for (int j = 0; j < 4; ++j) acc2[p][j] = 0ull;

#pragma unroll 1
    for (int t = 0; t < 8; ++t) {
        const bool second = (t >= 4);
        const int  kloc   = (t & 3) * 32;
        const float* W = second ? g_wr_eff : Wl;

        // stage A tile only for the hprev half
        if (second) {
#pragma unroll
            for (int i = 0; i < 2; ++i) {
                int f  = tid + 256 * i;
                int r  = f >> 3;
                int c4 = f & 7;
                int grow = row0 + r;
                float4 v = make_float4(0.f, 0.f, 0.f, 0.f);
                if (grow < N_NODES)
                    v = *((const float4*)(hprev + (size_t)grow * HDIM + kloc + c4 * 4));
                As[(c4 * 4 + 0) * AS_STRIDE + r] = v.x;
                As[(c4 * 4 + 1) * AS_STRIDE + r] = v.y;
                As[(c4 * 4 + 2) * AS_STRIDE + r] = v.z;
                As[(c4 * 4 + 3) * AS_STRIDE + r] = v.w;
            }
        }
        // stage B tile (32 k x 128 cols)
        {
            const int kglb = second ? kloc : t * 32;  // k within W's 128-wide dim
#pragma unroll
            for (int i = 0; i < 4; ++i) {
                int f  = tid + 256 * i;
                int j  = f >> 3;
                int kq = f & 7;
                float4 w = *((const float4*)(W + (size_t)j * HDIM + kglb + kq * 4));
                Bs[(kq * 4 + 0) * 132 + j] = w.x;
                Bs[(kq * 4 + 1) * 132 + j] = w.y;
                Bs[(kq * 4 + 2) * 132 + j] = w.z;
                Bs[(kq * 4 + 3) * 132 + j] = w.w;
            }
        }
        __syncthreads();

        const float* abase = second ? As : (sAggT + (t * 32) * AS_STRIDE);
#pragma unroll
        for (int k = 0; k < 32; ++k) {
            const ull* ap = (const ull*)(abase + k * AS_STRIDE + ty * 8);
            ull a0 = ap[0], a1 = ap[1], a2 = ap[2], a3 = ap[3];
            float4 bv = *((const float4*)(Bs + k * 132 + tx * 4));
            ull b0 = dup2(bv.x), b1 = dup2(bv.y), b2 = dup2(bv.z), b3 = dup2(bv.w);
            acc2[0][0] = fma2(a0, b0, acc2[0][0]);
            acc2[0][1] = fma2(a0, b1, acc2[0][1]);
            acc2[0][2] = fma2(a0, b2, acc2[0][2]);
            acc2[0][3] = fma2(a0, b3, acc2[0][3]);
            acc2[1][0] = fma2(a1, b0, acc2[1][0]);
            acc2[1][1] = fma2(a1, b1, acc2[1][1]);
            acc2[1][2] = fma2(a1, b2, acc2[1][2]);
            acc2[1][3] = fma2(a1, b3, acc2[1][3]);
            acc2[2][0] = fma2(a2, b0, acc2[2][0]);
            acc2[2][1] = fma2(a2, b1, acc2[2][1]);
            acc2[2][2] = fma2(a2, b2, acc2[2][2]);
            acc2[2][3] = fma2(a2, b3, acc2[2][3]);
            acc2[3][0] = fma2(a3, b0, acc2[3][0]);
            acc2[3][1] = fma2(a3, b1, acc2[3][1]);
            acc2[3][2] = fma2(a3, b2, acc2[3][2]);
            acc2[3][3] = fma2(a3, b3, acc2[3][3]);
        }
        __syncthreads();
    }

    // ================= epilogue: bias + relu + store + BN stats ==============
    const int col = tx * 4;
    float4 bi = *((const float4*)(g_bias_eff + col));
    float cs[4] = {0.f, 0.f, 0.f, 0.f};
    float sq[4] = {0.f, 0.f, 0.f, 0.f};
#pragma unroll
    for (int p = 0; p < 4; ++p) {
        float lo[4], hi[4];
#pragma unroll
        for (int j = 0; j < 4; ++j) {
            lo[j] = __uint_as_float((unsigned)(acc2[p][j] & 0xffffffffull));
            hi[j] = __uint_as_float((unsigned)(acc2[p][j] >> 32));
        }
        int grow = row0 + ty * 8 + 2 * p;
        if (grow < N_NODES) {
            float4 r;
            r.x = fmaxf(lo[0] + bi.x, 0.f);
            r.y = fmaxf(lo[1] + bi.y, 0.f);
            r.z = fmaxf(lo[2] + bi.z, 0.f);
            r.w = fmaxf(lo[3] + bi.w, 0.f);
            *((float4*)(yout + (size_t)grow * HDIM + col)) = r;
            cs[0] += r.x; sq[0] += r.x * r.x;
            cs[1] += r.y; sq[1] += r.y * r.y;
            cs[2] += r.z; sq[2] += r.z * r.z;
            cs[3] += r.w; sq[3] += r.w * r.w;
        }
        if (grow + 1 < N_NODES) {
            float4 r;
            r.x = fmaxf(hi[0] + bi.x, 0.f);
            r.y = fmaxf(hi[1] + bi.y, 0.f);
            r.z = fmaxf(hi[2] + bi.z, 0.f);
            r.w = fmaxf(hi[3] + bi.w, 0.f);
            *((float4*)(yout + (size_t)(grow + 1) * HDIM + col)) = r;
            cs[0] += r.x; sq[0] += r.x * r.x;
            cs[1] += r.y; sq[1] += r.y * r.y;
            cs[2] += r.z; sq[2] += r.z * r.z;
            cs[3] += r.w; sq[3] += r.w * r.w;
        }
    }
    if (tid < HDIM) { s_cs[tid] = 0.f; s_sq[tid] = 0.f; }
    __syncthreads();
#pragma unroll
    for (int j = 0; j < 4; ++j) {
        atomicAdd(&s_cs[col + j], cs[j]);
        atomicAdd(&s_sq[col + j], sq[j]);
    }
    __syncthreads();
    if (tid < HDIM) {
        atomicAdd(&g_colsum[tid], s_cs[tid]);
        atomicAdd(&g_colsq [tid], s_sq[tid]);
    }
}

// ---------------- BN finalize -> affine --------------------------------------
__global__ void finalize_kernel(const float* __restrict__ gamma,
                                const float* __restrict__ beta) {
    int j = threadIdx.x;
    if (j >= HDIM) return;
    float s  = g_colsum[j];
    float q  = g_colsq[j];
    float mu  = s / (float)N_NODES;
    float var = q / (float)N_NODES - mu * mu;
    float a = gamma[j] * rsqrtf(var + BN_EPS);
    float b = beta[j] - mu * a;
    g_affa[j] = a;
    g_affb[j] = b;
    g_colsum[j] = 0.f;
    g_colsq [j] = 0.f;
}

// ---------------- pooling fused with FC --------------------------------------
__global__ void pool_kernel(const float* __restrict__ h,
                            const int* __restrict__ batch,
                            const float* __restrict__ fcw) {
    int gt   = blockIdx.x * blockDim.x + threadIdx.x;
    int node = gt >> 5;
    int lane = gt & 31;
    if (node >= N_NODES) return;
    float4 v = ((const float4*)h)[node * 32 + lane];
    float4 a = ((const float4*)g_affa)[lane];
    float4 b = ((const float4*)g_affb)[lane];
    float4 w = ((const float4*)fcw)[lane];
    float d = fmaf(v.x, a.x, b.x) * w.x
            + fmaf(v.y, a.y, b.y) * w.y
            + fmaf(v.z, a.z, b.z) * w.z
            + fmaf(v.w, a.w, b.w) * w.w;
#pragma unroll
    for (int off = 16; off; off >>= 1)
        d += __shfl_down_sync(0xffffffff, d, off);
    if (lane == 0) atomicAdd(&g_pool[batch[node]], d);
}

__global__ void out_kernel(const float* __restrict__ fcb, float* __restrict__ out) {
    int g = threadIdx.x;
    if (g < NGRAPHS) out[g] = 1.0f / (1.0f + expf(-(g_pool[g] + fcb[0])));
}

// ---------------- host launcher (graph-capturable) --------------------------
extern "C" void kernel_launch(void* const* d_in, const int* in_sizes, int n_in,
                              void* d_out, int out_size) {
    const float* x        = (const float*)d_in[0];
    const int*   ei       = (const int*)d_in[1];
    /* d_in[2] edge_attr unused */
    const int*   batch    = (const int*)d_in[3];
    const float* lin_l_w  = (const float*)d_in[4];
    const float* lin_l_b  = (const float*)d_in[5];
    const float* lin_r_w  = (const float*)d_in[6];
    const float* bn_gamma = (const float*)d_in[7];
    const float* bn_beta  = (const float*)d_in[8];
    const float* fc_w     = (const float*)d_in[9];
    const float* fc_b     = (const float*)d_in[10];
    float*       out      = (float*)d_out;

    static int smem_set = 0;
    if (!smem_set) {
        cudaFuncSetAttribute(gemm_fused_kernel,
                             cudaFuncAttributeMaxDynamicSharedMemorySize, SMEM_BYTES);
        smem_set = 1;
    }

    void *p_b0, *p_b1;
    cudaGetSymbolAddress(&p_b0, g_buf0);
    cudaGetSymbolAddress(&p_b1, g_buf1);
    float* bufs[2] = { (float*)p_b0, (float*)p_b1 };

    initzero_kernel<<<(N_NODES + 255) / 256, 256>>>();
    count_kernel<<<(N_EDGES + 255) / 256, 256>>>(ei);
    scan1_kernel<<<NSCAN, SCAN_B>>>();
    scan23_kernel<<<(N_NODES + 255) / 256, 256>>>();
    fill_kernel<<<(N_EDGES + 255) / 256, 256>>>(ei);

    const float* hprev = x;
    for (int l = 0; l < NLAYERS; ++l) {
        float* yout = bufs[l & 1];
        prep_kernel<<<HDIM, HDIM>>>(lin_r_w + (size_t)l * HDIM * HDIM,
                                    lin_l_b + (size_t)l * HDIM);
        gemm_fused_kernel<<<(N_NODES + 63) / 64, 256, SMEM_BYTES>>>(
            hprev,
            lin_l_w + (size_t)l * HDIM * HDIM,
            yout);
        finalize_kernel<<<1, HDIM>>>(bn_gamma + (size_t)l * HDIM,
                                     bn_beta  + (size_t)l * HDIM);
        hprev = yout;
    }
    pool_kernel<<<(N_NODES * 32 + 255) / 256, 256>>>(hprev, batch, fc_w);
    out_kernel<<<1, NGRAPHS>>>(fc_b, out);
}